// round 15
// baseline (speedup 1.0000x reference)
#include <cuda_runtime.h>
#include <cuda_fp16.h>
#include <cstdint>

// ============================================================================
// Problem constants
// ============================================================================
#define KDIM 4096
#define NDIM 4096
#define MDIM 4096        // B*S
#define NB   128         // N / 32
#define KB   128         // K / 32

#define STAGES 3
#define A_BYTES (256 * 32 * 2)     // 16384  A tile [256m x 32k] fp16
#define W_BYTES (32 * 32 * 2)      // 2048   W tile [32n x 32k] fp16
#define STAGE_BYTES (A_BYTES + W_BYTES)            // 18432
#define SMEM_BIAS  512                             // 128B (32 floats)
#define SMEM_STAGE 1024
#define SMEM_TOTAL (SMEM_STAGE + STAGES * STAGE_BYTES)  // 56320 -> 4 CTAs/SM

// ============================================================================
// Device globals
// ============================================================================
__device__ int g_bm[NB * KB];                    // block-active bitmap
__device__ int g_klist[NB * KB];                 // per-nb compacted kb list
__device__ int g_kcount[NB];                     // per-nb active count
__device__ __half g_dh[(size_t)MDIM * KDIM];     // data  fp16 (32MB)
__device__ __half g_wh[(size_t)NDIM * KDIM];     // weight fp16 (active blocks only)

// ============================================================================
// Helpers
// ============================================================================
__device__ __forceinline__ uint32_t smem_u32(const void* p) {
    uint32_t a;
    asm("{ .reg .u64 t; cvta.to.shared.u64 t, %1; cvt.u32.u64 %0, t; }"
        : "=r"(a) : "l"(p));
    return a;
}

#define SWZ(off) ((uint32_t)(off) ^ ((((uint32_t)(off)) >> 3) & 0x70))

__device__ __forceinline__ void cp_async16(uint32_t saddr, const void* gaddr) {
    asm volatile("cp.async.cg.shared.global [%0], [%1], 16;"
                 :: "r"(saddr), "l"(gaddr) : "memory");
}
#define CP_ASYNC_COMMIT() asm volatile("cp.async.commit_group;" ::: "memory")
#define CP_ASYNC_WAIT(n)  asm volatile("cp.async.wait_group %0;" :: "n"(n) : "memory")

__device__ __forceinline__ void ldsm_x4(uint32_t addr, uint32_t* r) {
    asm volatile("ldmatrix.sync.aligned.m8n8.x4.shared.b16 {%0,%1,%2,%3}, [%4];"
                 : "=r"(r[0]), "=r"(r[1]), "=r"(r[2]), "=r"(r[3]) : "r"(addr));
}

// m16n8k16 fp16 mma, FP16 accumulators (full-rate HMMA path)
__device__ __forceinline__ void mma_f16acc(uint32_t* c, const uint32_t* a,
                                           const uint32_t* b) {
    asm volatile(
        "mma.sync.aligned.m16n8k16.row.col.f16.f16.f16.f16 "
        "{%0,%1}, {%2,%3,%4,%5}, {%6,%7}, {%0,%1};"
        : "+r"(c[0]), "+r"(c[1])
        : "r"(a[0]), "r"(a[1]), "r"(a[2]), "r"(a[3]), "r"(b[0]), "r"(b[1]));
}

// ============================================================================
// Kernel 1 (fused prepass): 2 CTAs per nb row (half-K each) -> 256 CTAs.
// mask pool + active-weight convert (own half) + 1/256 data convert.
// ============================================================================
__global__ __launch_bounds__(512) void prepass_kernel(
    const int* __restrict__ mask, const float* __restrict__ weight,
    const float* __restrict__ data) {
    __shared__ int sm_bm[64];
    __shared__ int sm_list[64];
    __shared__ int sm_cnt;
    const int nb   = blockIdx.x >> 1;
    const int half = blockIdx.x & 1;
    const int tid = threadIdx.x;

    if (tid < 64) sm_bm[tid] = 0;
    __syncthreads();

    // --- phase 1: coalesced mask scan of this half (2048 ints/row) ---
    int acc = 0;
    const int* mrow = mask + (size_t)(nb * 32) * KDIM + half * 2048;
#pragma unroll 4
    for (int r = 0; r < 32; r++) {
        const int4* p = (const int4*)(mrow + (size_t)r * KDIM);
        int4 v = p[tid];
        acc |= v.x | v.y | v.z | v.w;
    }
    if (acc) sm_bm[tid >> 3] = 1;           // idempotent stores
    __syncthreads();

    // --- write bitmap + build local active list (global kb indices) ---
    if (tid < 64) g_bm[nb * KB + half * 64 + tid] = sm_bm[tid];
    if (tid == 0) {
        int c = 0;
        for (int i = 0; i < 64; i++)
            if (sm_bm[i]) sm_list[c++] = half * 64 + i;
        sm_cnt = c;
    }

    // --- phase 2 (independent): convert this CTA's 1/256 slice of data ---
    // 512 threads x 128 floats = 65536 floats per CTA.
    {
        const size_t cta_base = (size_t)blockIdx.x * 65536;
#pragma unroll
        for (int qk = 0; qk < 8; qk++) {
            size_t base = cta_base + ((size_t)qk * 512 + tid) * 16;
            const float4* s = (const float4*)(data + base);
            __half2 h[8];
#pragma unroll
            for (int i = 0; i < 4; i++) {
                float4 v = s[i];
                h[2 * i]     = __floats2half2_rn(v.x, v.y);
                h[2 * i + 1] = __floats2half2_rn(v.z, v.w);
            }
            uint4* d = (uint4*)(g_dh + base);
            d[0] = reinterpret_cast<uint4*>(h)[0];
            d[1] = reinterpret_cast<uint4*>(h)[1];
        }
    }
    __syncthreads();

    // --- phase 3: convert active weight blocks (32x32) to fp16 ---
    const int cnt = sm_cnt;
    const int row = tid >> 4;          // 0..31
    const int pos = (tid & 15) * 2;    // 0..30
    for (int j = 0; j < cnt; j++) {
        int kb = sm_list[j];
        size_t off = (size_t)(nb * 32 + row) * KDIM + (size_t)kb * 32 + pos;
        float2 v = *(const float2*)(weight + off);
        *(__half2*)(g_wh + off) = __floats2half2_rn(v.x, v.y);
    }
}

// ============================================================================
// Kernel 2: compact per-nb active kb list (deterministic order).
// ============================================================================
__global__ __launch_bounds__(1024) void compact_kernel() {
    int nb = blockIdx.x * 32 + (threadIdx.x >> 5);
    int lane = threadIdx.x & 31;
    int count = 0;
#pragma unroll
    for (int r = 0; r < 4; r++) {
        int kb = r * 32 + lane;
        int a = g_bm[nb * KB + kb];
        unsigned bal = __ballot_sync(0xffffffffu, a);
        int pos = count + __popc(bal & ((1u << lane) - 1u));
        if (a) g_klist[nb * KB + pos] = kb;
        count += __popc(bal);
    }
    if (lane == 0) g_kcount[nb] = count;
}

// ============================================================================
// Kernel 3: block-sparse GEMM, fp16-accum MMA + per-kb fp32 promotion.
// CTA: 256m x 32n, 4 warps (warp = 64m x 32n). 3-stage cp.async, 4 CTAs/SM.
// grid = (nb=128, mtile=16).
// ============================================================================
__global__ __launch_bounds__(128, 4) void gemm_sparse_kernel(
    const float* __restrict__ bias,   // [N]
    float* __restrict__ out) {        // [M, N]
    extern __shared__ char smem[];
    const uint32_t sb = smem_u32(smem);
    const int tid = threadIdx.x;
    const int wid = tid >> 5;
    const int lane = tid & 31;
    const int nb = blockIdx.x;
    const int mtile = blockIdx.y;

    const int cnt = g_kcount[nb];
    if (tid < KB) ((int*)smem)[tid] = g_klist[nb * KB + tid];
    if (tid < 32) ((float*)(smem + SMEM_BIAS))[tid] = bias[nb * 32 + tid];
    __syncthreads();
    const int* sk = (const int*)smem;

    const __half* Abase = g_dh + (size_t)(mtile * 256) * KDIM;
    const __half* Wbase = g_wh + (size_t)(nb * 32) * KDIM;

    // ---- stage loader: A 1024 + W 128 16B chunks over 128 threads ----
    auto load_stage = [&](int s, int kb) {
        const uint32_t aT = sb + SMEM_STAGE + s * STAGE_BYTES;
        const uint32_t wT = aT + A_BYTES;
        const __half* ag = Abase + kb * 32;
        const __half* wg = Wbase + kb * 32;
#pragma unroll
        for (int p = 0; p < 8; p++) {
            int c = tid + p * 128;           // 0..1023
            int row = c >> 2, cc = c & 3;
            cp_async16(aT + SWZ(row * 64 + cc * 16),
                       ag + (size_t)row * KDIM + cc * 8);
        }
        {
            int row = tid >> 2, cc = tid & 3;
            cp_async16(wT + SWZ(row * 64 + cc * 16),
                       wg + (size_t)row * KDIM + cc * 8);
        }
    };

    float c_[4][4][4] = {};   // fp32 accumulators [m16-tile][n8-tile][frag]

    // ---- prologue ----
#pragma unroll
    for (int s0 = 0; s0 < STAGES - 1; s0++) {
        if (s0 < cnt) load_stage(s0, sk[s0]);
        CP_ASYNC_COMMIT();
    }

    const int a_r  = (lane & 7) + ((lane >> 3) & 1) * 8;
    const int a_ch = lane >> 4;
    const int b_r  = ((lane >> 4) & 1) * 8 + (lane & 7);
    const int b_ch = (lane >> 3) & 1;

    int s = 0;
    for (int i = 0; i < cnt; i++) {
        CP_ASYNC_WAIT(STAGES - 2);
        __syncthreads();

        int jn = i + STAGES - 1;
        if (jn < cnt) {
            int sj = s + STAGES - 1; if (sj >= STAGES) sj -= STAGES;
            load_stage(sj, sk[jn]);
        }
        CP_ASYNC_COMMIT();

        const uint32_t aT = sb + SMEM_STAGE + s * STAGE_BYTES;
        const uint32_t wT = aT + A_BYTES;

        // B fragments for both k16 steps (4 LDSM)
        uint32_t bf[2][4][2];
#pragma unroll
        for (int j = 0; j < 2; j++) {
            uint32_t bx[4], by[4];
            int ch = 2 * j + b_ch;
            ldsm_x4(wT + SWZ(b_r * 64 + ch * 16), bx);          // nt0, nt1
            ldsm_x4(wT + SWZ((b_r + 16) * 64 + ch * 16), by);   // nt2, nt3
            bf[j][0][0] = bx[0]; bf[j][0][1] = bx[1];
            bf[j][1][0] = bx[2]; bf[j][1][1] = bx[3];
            bf[j][2][0] = by[0]; bf[j][2][1] = by[1];
            bf[j][3][0] = by[2]; bf[j][3][1] = by[3];
        }

#pragma unroll
        for (int mt = 0; mt < 4; mt++) {
            // A fragments for both k16 steps of this m16 tile
            uint32_t af[2][4];
            int row = wid * 64 + mt * 16 + a_r;
#pragma unroll
            for (int j = 0; j < 2; j++)
                ldsm_x4(aT + SWZ(row * 64 + (2 * j + a_ch) * 16), af[j]);

            // fp16 accumulation over this kb only (K=32)
            uint32_t hc[4][2] = {};
#pragma unroll
            for (int j = 0; j < 2; j++)
#pragma unroll
                for (int nt = 0; nt < 4; nt++)
                    mma_f16acc(hc[nt], af[j], bf[j][nt]);

            // promote to fp32 accumulators
#pragma unroll
            for (int nt = 0; nt < 4; nt++) {
                float2 lo = __half22float2(*(__half2*)&hc[nt][0]);
                float2 hi = __half22float2(*(__half2*)&hc[nt][1]);
                c_[mt][nt][0] += lo.x;
                c_[mt][nt][1] += lo.y;
                c_[mt][nt][2] += hi.x;
                c_[mt][nt][3] += hi.y;
            }
        }
        s++; if (s == STAGES) s = 0;
    }

    // ---- epilogue: add bias, store float2 pairs ----
    const float* sbias = (const float*)(smem + SMEM_BIAS);
    const int g = lane >> 2;
    const int qq = lane & 3;
#pragma unroll
    for (int mt = 0; mt < 4; mt++) {
        int row0 = mtile * 256 + wid * 64 + mt * 16 + g;
#pragma unroll
        for (int nt = 0; nt < 4; nt++) {
            int coll = nt * 8 + 2 * qq;
            float b0 = sbias[coll];
            float b1 = sbias[coll + 1];
            float2 v0 = make_float2(c_[mt][nt][0] + b0, c_[mt][nt][1] + b1);
            float2 v1 = make_float2(c_[mt][nt][2] + b0, c_[mt][nt][3] + b1);
            size_t col = (size_t)nb * 32 + coll;
            *(float2*)(out + (size_t)row0 * NDIM + col) = v0;
            *(float2*)(out + (size_t)(row0 + 8) * NDIM + col) = v1;
        }
    }
}

// ============================================================================
// Launch
// ============================================================================
extern "C" void kernel_launch(void* const* d_in, const int* in_sizes, int n_in,
                              void* d_out, int out_size) {
    const float* data   = (const float*)d_in[0];   // [B,S,K] -> [M,K]
    const int*   mask   = (const int*)d_in[1];     // [N,K]
    const float* weight = (const float*)d_in[2];   // [N,K]
    const float* bias   = (const float*)d_in[3];   // [N]
    float* out = (float*)d_out;                    // [M,N]

    prepass_kernel<<<2 * NB, 512>>>(mask, weight, data);
    compact_kernel<<<4, 1024>>>();

    cudaFuncSetAttribute(gemm_sparse_kernel,
                         cudaFuncAttributeMaxDynamicSharedMemorySize, SMEM_TOTAL);
    dim3 grid(NB, MDIM / 256);     // x = nb, y = mtile
    gemm_sparse_kernel<<<grid, 128, SMEM_TOTAL>>>(bias, out);
}